// round 10
// baseline (speedup 1.0000x reference)
#include <cuda_runtime.h>
#include <cuda_fp16.h>
#include <cstdint>

// ---------------------------------------------------------------------------
// myGRUCell fused kernel for GB300 (sm_103a harness, base sm_103 PTX target).
// tcgen05 unavailable at this PTX target; tensor work via mma.sync.m16n8k16
// (HMMA) + ldmatrix + cp.async.
//
// 5-stream formulation (h@W_rh computed ONCE, shared by r and z):
//   accR  = in@Wri^T      accRH = h@Wrh^T
//   accZ  = in@Wzi^T      accN  = in@Wni^T      accH = h@Wnh^T
//   r  = sigmoid(accR + accRH + b_ri + b_rh)
//   z  = sigmoid(accZ + accRH + b_zi + b_rh)    (reference bug: reuses r_h)
//   n  = tanh   (accN + b_ni + r*(accH + b_nh))
//   out = (1-z)*n + z*h    (written twice: tuple output)
//
// R9: software-pipelined fragment loads (B double-buffer + hoisted A reloads)
// to hide LDSM latency behind HMMA issue. Prev: load_b -> 4 dependent mma
// serial beat kept tensor pipe at ~61%.
// ---------------------------------------------------------------------------

#define B_DIM 16384
#define K_DIM 1024
#define H_DIM 1024

// fp16 scratch (device globals: allocation-free per harness rules)
__device__ __half g_in[(size_t)B_DIM * K_DIM];
__device__ __half g_h [(size_t)B_DIM * K_DIM];
__device__ __half g_w [5][(size_t)H_DIM * K_DIM];   // ri, rh, zi, ni, nh

// ---- smem stage layout (BK = 64 halves = 128 bytes/row) ----
#define OFF_AIN 0            // A_in: 128 rows x 128B = 16KB
#define OFF_AH  16384        // A_h : 16KB
#define OFF_W   32768        // 5 weights x (64 rows x 128B = 8KB) = 40KB
#define STAGE_BYTES 73728    // 72KB
#define NSTAGE 3
#define SMEM_BYTES (STAGE_BYTES * NSTAGE)   // 216KB

// ---------------- PTX helpers (base sm_103 instruction set only) ------------
__device__ __forceinline__ uint32_t smem_u32(const void* p) {
    uint32_t a;
    asm("{ .reg .u64 t; cvta.to.shared.u64 t, %1; cvt.u32.u64 %0, t; }"
        : "=r"(a) : "l"(p));
    return a;
}
__device__ __forceinline__ void cp16(uint32_t saddr, const void* g) {
    asm volatile("cp.async.cg.shared.global [%0], [%1], 16;\n"
                 :: "r"(saddr), "l"(g));
}
__device__ __forceinline__ void cp_commit() {
    asm volatile("cp.async.commit_group;" ::: "memory");
}
template <int N>
__device__ __forceinline__ void cp_wait() {
    asm volatile("cp.async.wait_group %0;" :: "n"(N) : "memory");
}
__device__ __forceinline__ uint32_t swz(uint32_t byte) {
    return byte ^ ((byte >> 3) & 0x70u);
}
#define LDSM4(R, addr)                                                         \
    asm volatile("ldmatrix.sync.aligned.m8n8.x4.shared.b16 {%0,%1,%2,%3}, [%4];" \
        : "=r"((R)[0]), "=r"((R)[1]), "=r"((R)[2]), "=r"((R)[3]) : "r"(addr))

__device__ __forceinline__ void mma16816(float* c, const uint32_t* a,
                                         const uint32_t* b) {
    asm volatile(
        "mma.sync.aligned.m16n8k16.row.col.f32.f16.f16.f32 "
        "{%0,%1,%2,%3}, {%4,%5,%6,%7}, {%8,%9}, {%0,%1,%2,%3};"
        : "+f"(c[0]), "+f"(c[1]), "+f"(c[2]), "+f"(c[3])
        : "r"(a[0]), "r"(a[1]), "r"(a[2]), "r"(a[3]), "r"(b[0]), "r"(b[1]));
}

// one MMA stream step: warp tile 32x16, A frags a[2][4], B frag bw[4]
__device__ __forceinline__ void mma_block(float (&acc)[2][2][4],
                                          const uint32_t (&a)[2][4],
                                          const uint32_t (&bw)[4]) {
#pragma unroll
    for (int mi = 0; mi < 2; mi++) {
        mma16816(acc[mi][0], a[mi], &bw[0]);
        mma16816(acc[mi][1], a[mi], &bw[2]);
    }
}

// A fragments: m16k16 x2 (warp rows 32), row-major, SW128-swizzled smem
__device__ __forceinline__ void load_a(uint32_t (&a)[2][4], uint32_t abase,
                                       int warp_m, int kk, int lane) {
#pragma unroll
    for (int mi = 0; mi < 2; mi++) {
        uint32_t row = (uint32_t)(warp_m * 32 + mi * 16 + (lane & 15));
        uint32_t byte = row * 128u + (uint32_t)kk * 32u + ((uint32_t)(lane >> 4) << 4);
        LDSM4(a[mi], abase + swz(byte));
    }
}

// B fragments: n16 x k16 from W tile ((n,k) row-major); one ldmatrix.x4
__device__ __forceinline__ void load_b(uint32_t (&bw)[4], uint32_t wbase,
                                       int warp_n, int kk, int lane) {
    int g = lane >> 3;
    uint32_t row = (uint32_t)(warp_n * 16 + ((g >> 1) << 3) + (lane & 7));
    uint32_t byte = row * 128u + (uint32_t)kk * 32u + ((uint32_t)(g & 1) << 4);
    LDSM4(bw, wbase + swz(byte));
}

// ---------------- fp32 -> fp16 conversion ----------------
// activations: blockIdx.y = 0 -> input, 1 -> hidden
__global__ void cvt2_kernel(const float4* __restrict__ s0,
                            const float4* __restrict__ s1,
                            uint2* __restrict__ d0, uint2* __restrict__ d1,
                            int n4) {
    int i = blockIdx.x * blockDim.x + threadIdx.x;
    if (i < n4) {
        const float4* s = blockIdx.y ? s1 : s0;
        uint2* d = blockIdx.y ? d1 : d0;
        float4 v = s[i];
        __half2 a = __floats2half2_rn(v.x, v.y);
        __half2 b = __floats2half2_rn(v.z, v.w);
        uint2 u;
        u.x = *reinterpret_cast<uint32_t*>(&a);
        u.y = *reinterpret_cast<uint32_t*>(&b);
        d[i] = u;
    }
}

// all 5 weights in one launch: blockIdx.y selects the weight
__global__ void cvt5_kernel(const float4* __restrict__ s0,
                            const float4* __restrict__ s1,
                            const float4* __restrict__ s2,
                            const float4* __restrict__ s3,
                            const float4* __restrict__ s4,
                            uint2* __restrict__ dst, int n4) {
    const float4* srcs[5] = {s0, s1, s2, s3, s4};
    int i = blockIdx.x * blockDim.x + threadIdx.x;
    if (i < n4) {
        float4 v = srcs[blockIdx.y][i];
        __half2 a = __floats2half2_rn(v.x, v.y);
        __half2 b = __floats2half2_rn(v.z, v.w);
        uint2 u;
        u.x = *reinterpret_cast<uint32_t*>(&a);
        u.y = *reinterpret_cast<uint32_t*>(&b);
        dst[(size_t)blockIdx.y * n4 + i] = u;
    }
}

// ---------------- stage loader (512 threads): 9 cp.async per thread --------
__device__ __forceinline__ void load_stage(uint32_t sbase, int m_base,
                                           int n_base, int k0, int tid) {
    const int seg = tid & 7;      // 16B segment within a 128B row
    const int r0 = tid >> 3;      // 0..63
    const __half* gi = g_in + (size_t)m_base * 1024 + k0 + seg * 8;
    const __half* gh = g_h  + (size_t)m_base * 1024 + k0 + seg * 8;
#pragma unroll
    for (int it = 0; it < 2; it++) {
        uint32_t row = (uint32_t)(r0 + it * 64);
        uint32_t sw = swz(row * 128u + (uint32_t)seg * 16u);
        cp16(sbase + OFF_AIN + sw, gi + (size_t)row * 1024);
        cp16(sbase + OFF_AH  + sw, gh + (size_t)row * 1024);
    }
    const uint32_t sww = swz((uint32_t)r0 * 128u + (uint32_t)seg * 16u);
#pragma unroll
    for (int w = 0; w < 5; w++) {
        const __half* gw = g_w[w] + (size_t)(n_base + r0) * 1024 + k0 + seg * 8;
        cp16(sbase + OFF_W + w * 8192 + sww, gw);
    }
    cp_commit();
}

// ---------------- fused GRU kernel ----------------
// grid: (H/64, B/128); block: 512 threads; warp grid 4(m) x 4(n), warp 32x16
__global__ void __launch_bounds__(512, 1)
gru_kernel(const float* __restrict__ hidden_f32,
           const float* __restrict__ b_r_i, const float* __restrict__ b_r_h,
           const float* __restrict__ b_z_i, const float* __restrict__ b_n_i,
           const float* __restrict__ b_n_h,
           float* __restrict__ out, int write2) {
    extern __shared__ __align__(1024) char smem[];
    const int tid = threadIdx.x;
    const int wid = tid >> 5;
    const int lane = tid & 31;
    const int warp_m = wid >> 2;   // 0..3
    const int warp_n = wid & 3;    // 0..3
    const int m_base = blockIdx.y * 128;
    const int n_base = blockIdx.x * 64;
    const uint32_t sb = smem_u32(smem);

    // 5 accumulator streams (h@W_rh computed once, shared by r and z)
    float accR[2][2][4], accZ[2][2][4], accN[2][2][4], accH[2][2][4],
          accRH[2][2][4];
#pragma unroll
    for (int mi = 0; mi < 2; mi++)
#pragma unroll
        for (int ni = 0; ni < 2; ni++)
#pragma unroll
            for (int j = 0; j < 4; j++) {
                accR[mi][ni][j] = 0.f;  accZ[mi][ni][j] = 0.f;
                accN[mi][ni][j] = 0.f;  accH[mi][ni][j] = 0.f;
                accRH[mi][ni][j] = 0.f;
            }

    // prologue: 2 stages in flight
    load_stage(sb + 0 * STAGE_BYTES, m_base, n_base, 0, tid);
    load_stage(sb + 1 * STAGE_BYTES, m_base, n_base, 64, tid);

#pragma unroll 1
    for (int s = 0; s < 16; s++) {
        if (s >= 15) cp_wait<0>(); else cp_wait<1>();
        __syncthreads();
        // Buffer (s+2)%3 == (s-1)%3 was fully consumed before this barrier
        // (every warp finished stage s-1 before arriving): one sync/stage.
        if (s < 14)
            load_stage(sb + ((s + 2) % NSTAGE) * STAGE_BYTES,
                       m_base, n_base, (s + 2) * 64, tid);
        const uint32_t st = sb + (s % NSTAGE) * STAGE_BYTES;
        const uint32_t wt = st + OFF_W;

        // ---- software-pipelined mainloop: B double-buffered, A hoisted ----
        uint32_t ain[2][4], ah[2][4], bw[2][4];
        load_a(ain, st + OFF_AIN, warp_m, 0, lane);
        load_a(ah,  st + OFF_AH,  warp_m, 0, lane);
        load_b(bw[0], wt + 0 * 8192, warp_n, 0, lane);     // R frag, kk=0
        int cur = 0;                                        // 20 flips/stage: even
#pragma unroll
        for (int kk = 0; kk < 4; kk++) {
            // R: prefetch Z, consume R
            load_b(bw[cur ^ 1], wt + 2 * 8192, warp_n, kk, lane);
            mma_block(accR, ain, bw[cur]);  cur ^= 1;
            // Z: prefetch N
            load_b(bw[cur ^ 1], wt + 3 * 8192, warp_n, kk, lane);
            mma_block(accZ, ain, bw[cur]);  cur ^= 1;
            // N: prefetch RH; ain dead after this -> reload for kk+1
            load_b(bw[cur ^ 1], wt + 1 * 8192, warp_n, kk, lane);
            mma_block(accN, ain, bw[cur]);  cur ^= 1;
            if (kk < 3) load_a(ain, st + OFF_AIN, warp_m, kk + 1, lane);
            // RH: prefetch H
            load_b(bw[cur ^ 1], wt + 4 * 8192, warp_n, kk, lane);
            mma_block(accRH, ah, bw[cur]);  cur ^= 1;
            // H: prefetch next kk's R; ah dead after this -> reload
            if (kk < 3) load_b(bw[cur ^ 1], wt + 0 * 8192, warp_n, kk + 1, lane);
            mma_block(accH, ah, bw[cur]);   cur ^= 1;
            if (kk < 3) load_a(ah, st + OFF_AH, warp_m, kk + 1, lane);
        }
    }

    // -------- fused epilogue --------
    const int r_lane = lane >> 2;          // 0..7
    const int c_lane = (lane & 3) * 2;     // 0,2,4,6
    const size_t out2 = (size_t)B_DIM * H_DIM;

#pragma unroll
    for (int ni = 0; ni < 2; ni++) {
        const int gcol = n_base + warp_n * 16 + ni * 8 + c_lane;
        float bri0 = __ldg(&b_r_i[gcol]),     bri1 = __ldg(&b_r_i[gcol + 1]);
        float brh0 = __ldg(&b_r_h[gcol]),     brh1 = __ldg(&b_r_h[gcol + 1]);
        float bzi0 = __ldg(&b_z_i[gcol]),     bzi1 = __ldg(&b_z_i[gcol + 1]);
        float bni0 = __ldg(&b_n_i[gcol]),     bni1 = __ldg(&b_n_i[gcol + 1]);
        float bnh0 = __ldg(&b_n_h[gcol]),     bnh1 = __ldg(&b_n_h[gcol + 1]);
        const float br[2]  = {bri0 + brh0, bri1 + brh1};
        const float bz[2]  = {bzi0 + brh0, bzi1 + brh1};
        const float bn[2]  = {bni0, bni1};
        const float bh[2]  = {bnh0, bnh1};
#pragma unroll
        for (int mi = 0; mi < 2; mi++) {
#pragma unroll
            for (int half = 0; half < 2; half++) {
                const int grow = m_base + warp_m * 32 + mi * 16 + half * 8 + r_lane;
                const size_t rowoff = (size_t)grow * 1024 + gcol;
                const float2 h2 = *(const float2*)(hidden_f32 + rowoff);
                float o[2];
#pragma unroll
                for (int j = 0; j < 2; j++) {
                    const int c = half * 2 + j;
                    float rh = accRH[mi][ni][c];
                    float vr = accR[mi][ni][c] + rh + br[j];
                    float vz = accZ[mi][ni][c] + rh + bz[j];
                    float vn = accN[mi][ni][c] + bn[j];
                    float vh = accH[mi][ni][c] + bh[j];
                    float rg = 1.f / (1.f + __expf(-vr));
                    float zg = 1.f / (1.f + __expf(-vz));
                    float pre = vn + rg * vh;
                    float ng = 2.f / (1.f + __expf(-2.f * pre)) - 1.f;
                    float hv = j ? h2.y : h2.x;
                    o[j] = (1.f - zg) * ng + zg * hv;
                }
                float2 o2; o2.x = o[0]; o2.y = o[1];
                *(float2*)(out + rowoff) = o2;
                if (write2) *(float2*)(out + out2 + rowoff) = o2;
            }
        }
    }
}

// ---------------- host launch ----------------
extern "C" void kernel_launch(void* const* d_in, const int* in_sizes, int n_in,
                              void* d_out, int out_size) {
    const float* input  = (const float*)d_in[0];
    const float* hidden = (const float*)d_in[1];
    const float* W_r_i  = (const float*)d_in[2];
    const float* b_r_i  = (const float*)d_in[3];
    const float* W_r_h  = (const float*)d_in[4];
    const float* b_r_h  = (const float*)d_in[5];
    const float* W_z_i  = (const float*)d_in[6];
    const float* b_z_i  = (const float*)d_in[7];
    // d_in[8], d_in[9]: W_z_h / b_z_h — dead per reference bug
    const float* W_n_i  = (const float*)d_in[10];
    const float* b_n_i  = (const float*)d_in[11];
    const float* W_n_h  = (const float*)d_in[12];
    const float* b_n_h  = (const float*)d_in[13];
    float* out = (float*)d_out;

    void *pin, *ph, *pw;
    cudaGetSymbolAddress(&pin, g_in);
    cudaGetSymbolAddress(&ph, g_h);
    cudaGetSymbolAddress(&pw, g_w);

    const int act4 = (B_DIM * K_DIM) / 4;
    const int wt4  = (H_DIM * K_DIM) / 4;
    dim3 agrid(act4 / 256, 2);
    cvt2_kernel<<<agrid, 256>>>((const float4*)input, (const float4*)hidden,
                                (uint2*)pin, (uint2*)ph, act4);
    // weight order in g_w: ri, rh, zi, ni, nh
    dim3 wgrid(wt4 / 256, 5);
    cvt5_kernel<<<wgrid, 256>>>((const float4*)W_r_i, (const float4*)W_r_h,
                                (const float4*)W_z_i, (const float4*)W_n_i,
                                (const float4*)W_n_h, (uint2*)pw, wt4);

    cudaFuncSetAttribute(gru_kernel, cudaFuncAttributeMaxDynamicSharedMemorySize,
                         SMEM_BYTES);
    dim3 grid(H_DIM / 64, B_DIM / 128);   // (16, 128)
    int write2 = (out_size >= 2 * B_DIM * H_DIM) ? 1 : 0;
    gru_kernel<<<grid, 512, SMEM_BYTES>>>(hidden, b_r_i, b_r_h, b_z_i,
                                          b_n_i, b_n_h, out, write2);
}

// round 12
// speedup vs baseline: 1.1118x; 1.1118x over previous
#include <cuda_runtime.h>
#include <cuda_fp16.h>
#include <cstdint>

// ---------------------------------------------------------------------------
// myGRUCell fused kernel for GB300 (sm_103a harness, base sm_103 PTX target).
// tcgen05 unavailable at this PTX target; tensor work via mma.sync.m16n8k16
// (HMMA) + ldmatrix + cp.async.
//
// 5-stream formulation (h@W_rh computed ONCE, shared by r and z):
//   accR  = in@Wri^T      accRH = h@Wrh^T
//   accZ  = in@Wzi^T      accN  = in@Wni^T      accH = h@Wnh^T
//   r  = sigmoid(accR + accRH + b_ri + b_rh)
//   z  = sigmoid(accZ + accRH + b_zi + b_rh)    (reference bug: reuses r_h)
//   n  = tanh   (accN + b_ni + r*(accH + b_nh))
//   out = (1-z)*n + z*h    (written twice: tuple output)
//
// R12: R11's barrier-free mbarrier mainloop with the deadlock fixed —
// cp.async.mbarrier.arrive needs .noinc so the deferred arrive counts toward
// the init(512) expected arrivals (default form increments-then-decrements,
// net zero -> phase never completed -> hang).
// ---------------------------------------------------------------------------

#define B_DIM 16384
#define K_DIM 1024
#define H_DIM 1024

// fp16 scratch (device globals: allocation-free per harness rules)
__device__ __half g_in[(size_t)B_DIM * K_DIM];
__device__ __half g_h [(size_t)B_DIM * K_DIM];
__device__ __half g_w [5][(size_t)H_DIM * K_DIM];   // ri, rh, zi, ni, nh

// ---- smem stage layout (BK = 64 halves = 128 bytes/row) ----
#define OFF_AIN 0            // A_in: 128 rows x 128B = 16KB
#define OFF_AH  16384        // A_h : 16KB
#define OFF_W   32768        // 5 weights x (64 rows x 128B = 8KB) = 40KB
#define STAGE_BYTES 73728    // 72KB
#define NSTAGE 3
#define MBAR_OFF (NSTAGE * STAGE_BYTES)     // 6 mbarriers: full[3], empty[3]
#define SMEM_BYTES (MBAR_OFF + 64)

#define NTHREADS 512

// ---------------- PTX helpers (base sm_103 instruction set only) ------------
__device__ __forceinline__ uint32_t smem_u32(const void* p) {
    uint32_t a;
    asm("{ .reg .u64 t; cvta.to.shared.u64 t, %1; cvt.u32.u64 %0, t; }"
        : "=r"(a) : "l"(p));
    return a;
}
__device__ __forceinline__ void cp16(uint32_t saddr, const void* g) {
    asm volatile("cp.async.cg.shared.global [%0], [%1], 16;\n"
                 :: "r"(saddr), "l"(g));
}
__device__ __forceinline__ void mbar_init(uint32_t a, uint32_t cnt) {
    asm volatile("mbarrier.init.shared.b64 [%0], %1;" :: "r"(a), "r"(cnt) : "memory");
}
// deferred arrive once all of this thread's prior cp.async have completed.
// .noinc: the arrive decrements the expected count set at init (CUTLASS
// cpasync_barrier_arrive form). Without .noinc the count is incremented at
// issue and the arrive nets to zero -> deadlock (R11).
__device__ __forceinline__ void cp_mbar_arrive(uint32_t a) {
    asm volatile("cp.async.mbarrier.arrive.noinc.shared.b64 [%0];" :: "r"(a) : "memory");
}
__device__ __forceinline__ void mbar_arrive(uint32_t a) {
    asm volatile("mbarrier.arrive.shared.b64 _, [%0];" :: "r"(a) : "memory");
}
// completes when the phase with the given parity completes (acquire)
__device__ __forceinline__ void mbar_wait(uint32_t a, uint32_t parity) {
    uint32_t done;
    asm volatile("{\n\t.reg .pred p;\n\t"
                 "mbarrier.try_wait.parity.acquire.cta.shared::cta.b64 p, [%1], %2;\n\t"
                 "selp.b32 %0, 1, 0, p;\n\t}"
                 : "=r"(done) : "r"(a), "r"(parity) : "memory");
    if (!done) {
        asm volatile("{\n\t.reg .pred P1;\n\t"
                     "W_%=:\n\t"
                     "mbarrier.try_wait.parity.acquire.cta.shared::cta.b64 P1, [%0], %1, 0x989680;\n\t"
                     "@P1 bra.uni D_%=;\n\t"
                     "bra.uni W_%=;\n\t"
                     "D_%=:\n\t}" :: "r"(a), "r"(parity) : "memory");
    }
}
__device__ __forceinline__ uint32_t swz(uint32_t byte) {
    return byte ^ ((byte >> 3) & 0x70u);
}
#define LDSM4(R, addr)                                                         \
    asm volatile("ldmatrix.sync.aligned.m8n8.x4.shared.b16 {%0,%1,%2,%3}, [%4];" \
        : "=r"((R)[0]), "=r"((R)[1]), "=r"((R)[2]), "=r"((R)[3]) : "r"(addr))

__device__ __forceinline__ void mma16816(float* c, const uint32_t* a,
                                         const uint32_t* b) {
    asm volatile(
        "mma.sync.aligned.m16n8k16.row.col.f32.f16.f16.f32 "
        "{%0,%1,%2,%3}, {%4,%5,%6,%7}, {%8,%9}, {%0,%1,%2,%3};"
        : "+f"(c[0]), "+f"(c[1]), "+f"(c[2]), "+f"(c[3])
        : "r"(a[0]), "r"(a[1]), "r"(a[2]), "r"(a[3]), "r"(b[0]), "r"(b[1]));
}

// one MMA stream step: warp tile 32x16, A frags a[2][4], B frag bw[4]
__device__ __forceinline__ void mma_block(float (&acc)[2][2][4],
                                          const uint32_t (&a)[2][4],
                                          const uint32_t (&bw)[4]) {
#pragma unroll
    for (int mi = 0; mi < 2; mi++) {
        mma16816(acc[mi][0], a[mi], &bw[0]);
        mma16816(acc[mi][1], a[mi], &bw[2]);
    }
}

// A fragments: m16k16 x2 (warp rows 32), row-major, SW128-swizzled smem
__device__ __forceinline__ void load_a(uint32_t (&a)[2][4], uint32_t abase,
                                       int warp_m, int kk, int lane) {
#pragma unroll
    for (int mi = 0; mi < 2; mi++) {
        uint32_t row = (uint32_t)(warp_m * 32 + mi * 16 + (lane & 15));
        uint32_t byte = row * 128u + (uint32_t)kk * 32u + ((uint32_t)(lane >> 4) << 4);
        LDSM4(a[mi], abase + swz(byte));
    }
}

// B fragments: n16 x k16 from W tile ((n,k) row-major); one ldmatrix.x4
__device__ __forceinline__ void load_b(uint32_t (&bw)[4], uint32_t wbase,
                                       int warp_n, int kk, int lane) {
    int g = lane >> 3;
    uint32_t row = (uint32_t)(warp_n * 16 + ((g >> 1) << 3) + (lane & 7));
    uint32_t byte = row * 128u + (uint32_t)kk * 32u + ((uint32_t)(g & 1) << 4);
    LDSM4(bw, wbase + swz(byte));
}

// ---------------- fp32 -> fp16 conversion ----------------
// activations: blockIdx.y = 0 -> input, 1 -> hidden
__global__ void cvt2_kernel(const float4* __restrict__ s0,
                            const float4* __restrict__ s1,
                            uint2* __restrict__ d0, uint2* __restrict__ d1,
                            int n4) {
    int i = blockIdx.x * blockDim.x + threadIdx.x;
    if (i < n4) {
        const float4* s = blockIdx.y ? s1 : s0;
        uint2* d = blockIdx.y ? d1 : d0;
        float4 v = s[i];
        __half2 a = __floats2half2_rn(v.x, v.y);
        __half2 b = __floats2half2_rn(v.z, v.w);
        uint2 u;
        u.x = *reinterpret_cast<uint32_t*>(&a);
        u.y = *reinterpret_cast<uint32_t*>(&b);
        d[i] = u;
    }
}

// all 5 weights in one launch: blockIdx.y selects the weight
__global__ void cvt5_kernel(const float4* __restrict__ s0,
                            const float4* __restrict__ s1,
                            const float4* __restrict__ s2,
                            const float4* __restrict__ s3,
                            const float4* __restrict__ s4,
                            uint2* __restrict__ dst, int n4) {
    const float4* srcs[5] = {s0, s1, s2, s3, s4};
    int i = blockIdx.x * blockDim.x + threadIdx.x;
    if (i < n4) {
        float4 v = srcs[blockIdx.y][i];
        __half2 a = __floats2half2_rn(v.x, v.y);
        __half2 b = __floats2half2_rn(v.z, v.w);
        uint2 u;
        u.x = *reinterpret_cast<uint32_t*>(&a);
        u.y = *reinterpret_cast<uint32_t*>(&b);
        dst[(size_t)blockIdx.y * n4 + i] = u;
    }
}

// ---------------- stage loader (512 threads): 9 cp.async per thread --------
__device__ __forceinline__ void load_stage(uint32_t sbase, int m_base,
                                           int n_base, int k0, int tid) {
    const int seg = tid & 7;      // 16B segment within a 128B row
    const int r0 = tid >> 3;      // 0..63
    const __half* gi = g_in + (size_t)m_base * 1024 + k0 + seg * 8;
    const __half* gh = g_h  + (size_t)m_base * 1024 + k0 + seg * 8;
#pragma unroll
    for (int it = 0; it < 2; it++) {
        uint32_t row = (uint32_t)(r0 + it * 64);
        uint32_t sw = swz(row * 128u + (uint32_t)seg * 16u);
        cp16(sbase + OFF_AIN + sw, gi + (size_t)row * 1024);
        cp16(sbase + OFF_AH  + sw, gh + (size_t)row * 1024);
    }
    const uint32_t sww = swz((uint32_t)r0 * 128u + (uint32_t)seg * 16u);
#pragma unroll
    for (int w = 0; w < 5; w++) {
        const __half* gw = g_w[w] + (size_t)(n_base + r0) * 1024 + k0 + seg * 8;
        cp16(sbase + OFF_W + w * 8192 + sww, gw);
    }
}

// ---------------- fused GRU kernel ----------------
// grid: (H/64, B/128); block: 512 threads; warp grid 4(m) x 4(n), warp 32x16
__global__ void __launch_bounds__(512, 1)
gru_kernel(const float* __restrict__ hidden_f32,
           const float* __restrict__ b_r_i, const float* __restrict__ b_r_h,
           const float* __restrict__ b_z_i, const float* __restrict__ b_n_i,
           const float* __restrict__ b_n_h,
           float* __restrict__ out, int write2) {
    extern __shared__ __align__(1024) char smem[];
    const int tid = threadIdx.x;
    const int wid = tid >> 5;
    const int lane = tid & 31;
    const int warp_m = wid >> 2;   // 0..3
    const int warp_n = wid & 3;    // 0..3
    const int m_base = blockIdx.y * 128;
    const int n_base = blockIdx.x * 64;
    const uint32_t sb = smem_u32(smem);
    const uint32_t mb_full  = sb + MBAR_OFF;        // full[b]  = mb_full + 8b
    const uint32_t mb_empty = sb + MBAR_OFF + 24;   // empty[b] = mb_empty + 8b

    if (tid == 0) {
#pragma unroll
        for (int b = 0; b < NSTAGE; b++) {
            mbar_init(mb_full + 8 * b, NTHREADS);   // 1 cp-arrive per thread
            mbar_init(mb_empty + 8 * b, NTHREADS);  // 1 arrive per thread
        }
    }
    __syncthreads();   // mbarriers visible before any arrive

    // 5 accumulator streams (h@W_rh computed once, shared by r and z)
    float accR[2][2][4], accZ[2][2][4], accN[2][2][4], accH[2][2][4],
          accRH[2][2][4];
#pragma unroll
    for (int mi = 0; mi < 2; mi++)
#pragma unroll
        for (int ni = 0; ni < 2; ni++)
#pragma unroll
            for (int j = 0; j < 4; j++) {
                accR[mi][ni][j] = 0.f;  accZ[mi][ni][j] = 0.f;
                accN[mi][ni][j] = 0.f;  accH[mi][ni][j] = 0.f;
                accRH[mi][ni][j] = 0.f;
            }

    // prologue: fill stages 0 and 1 (first use -> no empty wait needed)
    load_stage(sb + 0 * STAGE_BYTES, m_base, n_base, 0, tid);
    cp_mbar_arrive(mb_full + 0);
    load_stage(sb + 1 * STAGE_BYTES, m_base, n_base, 64, tid);
    cp_mbar_arrive(mb_full + 8);

#pragma unroll 1
    for (int s = 0; s < 16; s++) {
        const int b = s % NSTAGE;
        const uint32_t pf = (uint32_t)((s / NSTAGE) & 1);  // full parity
        mbar_wait(mb_full + 8 * b, pf);

        const uint32_t st = sb + b * STAGE_BYTES;
        const uint32_t wt = st + OFF_W;
#pragma unroll
        for (int kk = 0; kk < 4; kk++) {
            uint32_t ain[2][4], ah[2][4], bw[4];
            load_a(ain, st + OFF_AIN, warp_m, kk, lane);
            load_a(ah,  st + OFF_AH,  warp_m, kk, lane);

            load_b(bw, wt + 0 * 8192, warp_n, kk, lane);  // W_ri
            mma_block(accR, ain, bw);
            load_b(bw, wt + 2 * 8192, warp_n, kk, lane);  // W_zi
            mma_block(accZ, ain, bw);
            load_b(bw, wt + 3 * 8192, warp_n, kk, lane);  // W_ni
            mma_block(accN, ain, bw);
            load_b(bw, wt + 1 * 8192, warp_n, kk, lane);  // W_rh
            mma_block(accRH, ah, bw);                     // shared r/z
            load_b(bw, wt + 4 * 8192, warp_n, kk, lane);  // W_nh
            mma_block(accH, ah, bw);
        }
        mbar_arrive(mb_empty + 8 * b);   // release: LDSMs of buf b done

        if (s < 14) {
            const int t = s + 2;
            const int bt = t % NSTAGE;
            // wait for (load#-1)-th consume; passes immediately for load#0
            const uint32_t pe = (uint32_t)(((t / NSTAGE) + 1) & 1);
            mbar_wait(mb_empty + 8 * bt, pe);
            load_stage(sb + bt * STAGE_BYTES, m_base, n_base, t * 64, tid);
            cp_mbar_arrive(mb_full + 8 * bt);
        }
    }

    // -------- fused epilogue (accs in regs; no CTA sync needed) --------
    const int r_lane = lane >> 2;          // 0..7
    const int c_lane = (lane & 3) * 2;     // 0,2,4,6
    const size_t out2 = (size_t)B_DIM * H_DIM;

#pragma unroll
    for (int ni = 0; ni < 2; ni++) {
        const int gcol = n_base + warp_n * 16 + ni * 8 + c_lane;
        float bri0 = __ldg(&b_r_i[gcol]),     bri1 = __ldg(&b_r_i[gcol + 1]);
        float brh0 = __ldg(&b_r_h[gcol]),     brh1 = __ldg(&b_r_h[gcol + 1]);
        float bzi0 = __ldg(&b_z_i[gcol]),     bzi1 = __ldg(&b_z_i[gcol + 1]);
        float bni0 = __ldg(&b_n_i[gcol]),     bni1 = __ldg(&b_n_i[gcol + 1]);
        float bnh0 = __ldg(&b_n_h[gcol]),     bnh1 = __ldg(&b_n_h[gcol + 1]);
        const float br[2]  = {bri0 + brh0, bri1 + brh1};
        const float bz[2]  = {bzi0 + brh0, bzi1 + brh1};
        const float bn[2]  = {bni0, bni1};
        const float bh[2]  = {bnh0, bnh1};
#pragma unroll
        for (int mi = 0; mi < 2; mi++) {
#pragma unroll
            for (int half = 0; half < 2; half++) {
                const int grow = m_base + warp_m * 32 + mi * 16 + half * 8 + r_lane;
                const size_t rowoff = (size_t)grow * 1024 + gcol;
                const float2 h2 = *(const float2*)(hidden_f32 + rowoff);
                float o[2];
#pragma unroll
                for (int j = 0; j < 2; j++) {
                    const int c = half * 2 + j;
                    float rh = accRH[mi][ni][c];
                    float vr = accR[mi][ni][c] + rh + br[j];
                    float vz = accZ[mi][ni][c] + rh + bz[j];
                    float vn = accN[mi][ni][c] + bn[j];
                    float vh = accH[mi][ni][c] + bh[j];
                    float rg = 1.f / (1.f + __expf(-vr));
                    float zg = 1.f / (1.f + __expf(-vz));
                    float pre = vn + rg * vh;
                    float ng = 2.f / (1.f + __expf(-2.f * pre)) - 1.f;
                    float hv = j ? h2.y : h2.x;
                    o[j] = (1.f - zg) * ng + zg * hv;
                }
                float2 o2; o2.x = o[0]; o2.y = o[1];
                *(float2*)(out + rowoff) = o2;
                if (write2) *(float2*)(out + out2 + rowoff) = o2;
            }
        }
    }
}

// ---------------- host launch ----------------
extern "C" void kernel_launch(void* const* d_in, const int* in_sizes, int n_in,
                              void* d_out, int out_size) {
    const float* input  = (const float*)d_in[0];
    const float* hidden = (const float*)d_in[1];
    const float* W_r_i  = (const float*)d_in[2];
    const float* b_r_i  = (const float*)d_in[3];
    const float* W_r_h  = (const float*)d_in[4];
    const float* b_r_h  = (const float*)d_in[5];
    const float* W_z_i  = (const float*)d_in[6];
    const float* b_z_i  = (const float*)d_in[7];
    // d_in[8], d_in[9]: W_z_h / b_z_h — dead per reference bug
    const float* W_n_i  = (const float*)d_in[10];
    const float* b_n_i  = (const float*)d_in[11];
    const float* W_n_h  = (const float*)d_in[12];
    const float* b_n_h  = (const float*)d_in[13];
    float* out = (float*)d_out;

    void *pin, *ph, *pw;
    cudaGetSymbolAddress(&pin, g_in);
    cudaGetSymbolAddress(&ph, g_h);
    cudaGetSymbolAddress(&pw, g_w);

    const int act4 = (B_DIM * K_DIM) / 4;
    const int wt4  = (H_DIM * K_DIM) / 4;
    dim3 agrid(act4 / 256, 2);
    cvt2_kernel<<<agrid, 256>>>((const float4*)input, (const float4*)hidden,
                                (uint2*)pin, (uint2*)ph, act4);
    // weight order in g_w: ri, rh, zi, ni, nh
    dim3 wgrid(wt4 / 256, 5);
    cvt5_kernel<<<wgrid, 256>>>((const float4*)W_r_i, (const float4*)W_r_h,
                                (const float4*)W_z_i, (const float4*)W_n_i,
                                (const float4*)W_n_h, (uint2*)pw, wt4);

    cudaFuncSetAttribute(gru_kernel, cudaFuncAttributeMaxDynamicSharedMemorySize,
                         SMEM_BYTES);
    dim3 grid(H_DIM / 64, B_DIM / 128);   // (16, 128)
    int write2 = (out_size >= 2 * B_DIM * H_DIM) ? 1 : 0;
    gru_kernel<<<grid, NTHREADS, SMEM_BYTES>>>(hidden, b_r_i, b_r_h, b_z_i,
                                               b_n_i, b_n_h, out, write2);
}

// round 13
// speedup vs baseline: 1.1397x; 1.0250x over previous
#include <cuda_runtime.h>
#include <cuda_fp16.h>
#include <cstdint>

// ---------------------------------------------------------------------------
// myGRUCell fused kernel for GB300 (sm_103a harness, base sm_103 PTX target).
// tcgen05 unavailable at this PTX target; tensor work via mma.sync.m16n8k16
// (HMMA) + ldmatrix + cp.async.
//
// 5-stream formulation (h@W_rh computed ONCE, shared by r and z):
//   accR  = in@Wri^T      accRH = h@Wrh^T
//   accZ  = in@Wzi^T      accN  = in@Wni^T      accH = h@Wnh^T
//   r  = sigmoid(accR + accRH + b_ri + b_rh)
//   z  = sigmoid(accZ + accRH + b_zi + b_rh)    (reference bug: reuses r_h)
//   n  = tanh   (accN + b_ni + r*(accH + b_nh))
//   out = (1-z)*n + z*h    (written twice: tuple output)
//
// R13: persistent CTAs (one per SM). Each CTA walks tiles c, c+g, c+2g...
// through ONE continuous mbarrier-paced 3-buffer cp.async pipeline; the
// 2-stage load lead crosses tile boundaries, so next tile's loads are in
// flight while this tile's epilogue runs. Removes ~13 wave transitions of
// pipeline drain/refill (R12: 2048 CTAs, ~14 waves).
// ---------------------------------------------------------------------------

#define B_DIM 16384
#define K_DIM 1024
#define H_DIM 1024
#define NTILES 2048            // (B/128) * (H/64) = 128 * 16

// fp16 scratch (device globals: allocation-free per harness rules)
__device__ __half g_in[(size_t)B_DIM * K_DIM];
__device__ __half g_h [(size_t)B_DIM * K_DIM];
__device__ __half g_w [5][(size_t)H_DIM * K_DIM];   // ri, rh, zi, ni, nh

// ---- smem stage layout (BK = 64 halves = 128 bytes/row) ----
#define OFF_AIN 0            // A_in: 128 rows x 128B = 16KB
#define OFF_AH  16384        // A_h : 16KB
#define OFF_W   32768        // 5 weights x (64 rows x 128B = 8KB) = 40KB
#define STAGE_BYTES 73728    // 72KB
#define NSTAGE 3
#define MBAR_OFF (NSTAGE * STAGE_BYTES)     // 6 mbarriers: full[3], empty[3]
#define SMEM_BYTES (MBAR_OFF + 64)

#define NTHREADS 512

// ---------------- PTX helpers (base sm_103 instruction set only) ------------
__device__ __forceinline__ uint32_t smem_u32(const void* p) {
    uint32_t a;
    asm("{ .reg .u64 t; cvta.to.shared.u64 t, %1; cvt.u32.u64 %0, t; }"
        : "=r"(a) : "l"(p));
    return a;
}
__device__ __forceinline__ void cp16(uint32_t saddr, const void* g) {
    asm volatile("cp.async.cg.shared.global [%0], [%1], 16;\n"
                 :: "r"(saddr), "l"(g));
}
__device__ __forceinline__ void mbar_init(uint32_t a, uint32_t cnt) {
    asm volatile("mbarrier.init.shared.b64 [%0], %1;" :: "r"(a), "r"(cnt) : "memory");
}
// deferred arrive once all of this thread's prior cp.async have completed.
// .noinc: counts toward the init() expected arrivals (default form nets zero
// -> deadlock, R11).
__device__ __forceinline__ void cp_mbar_arrive(uint32_t a) {
    asm volatile("cp.async.mbarrier.arrive.noinc.shared.b64 [%0];" :: "r"(a) : "memory");
}
__device__ __forceinline__ void mbar_arrive(uint32_t a) {
    asm volatile("mbarrier.arrive.shared.b64 _, [%0];" :: "r"(a) : "memory");
}
// completes when the phase with the given parity completes (acquire)
__device__ __forceinline__ void mbar_wait(uint32_t a, uint32_t parity) {
    uint32_t done;
    asm volatile("{\n\t.reg .pred p;\n\t"
                 "mbarrier.try_wait.parity.acquire.cta.shared::cta.b64 p, [%1], %2;\n\t"
                 "selp.b32 %0, 1, 0, p;\n\t}"
                 : "=r"(done) : "r"(a), "r"(parity) : "memory");
    if (!done) {
        asm volatile("{\n\t.reg .pred P1;\n\t"
                     "W_%=:\n\t"
                     "mbarrier.try_wait.parity.acquire.cta.shared::cta.b64 P1, [%0], %1, 0x989680;\n\t"
                     "@P1 bra.uni D_%=;\n\t"
                     "bra.uni W_%=;\n\t"
                     "D_%=:\n\t}" :: "r"(a), "r"(parity) : "memory");
    }
}
__device__ __forceinline__ uint32_t swz(uint32_t byte) {
    return byte ^ ((byte >> 3) & 0x70u);
}
#define LDSM4(R, addr)                                                         \
    asm volatile("ldmatrix.sync.aligned.m8n8.x4.shared.b16 {%0,%1,%2,%3}, [%4];" \
        : "=r"((R)[0]), "=r"((R)[1]), "=r"((R)[2]), "=r"((R)[3]) : "r"(addr))

__device__ __forceinline__ void mma16816(float* c, const uint32_t* a,
                                         const uint32_t* b) {
    asm volatile(
        "mma.sync.aligned.m16n8k16.row.col.f32.f16.f16.f32 "
        "{%0,%1,%2,%3}, {%4,%5,%6,%7}, {%8,%9}, {%0,%1,%2,%3};"
        : "+f"(c[0]), "+f"(c[1]), "+f"(c[2]), "+f"(c[3])
        : "r"(a[0]), "r"(a[1]), "r"(a[2]), "r"(a[3]), "r"(b[0]), "r"(b[1]));
}

// one MMA stream step: warp tile 32x16, A frags a[2][4], B frag bw[4]
__device__ __forceinline__ void mma_block(float (&acc)[2][2][4],
                                          const uint32_t (&a)[2][4],
                                          const uint32_t (&bw)[4]) {
#pragma unroll
    for (int mi = 0; mi < 2; mi++) {
        mma16816(acc[mi][0], a[mi], &bw[0]);
        mma16816(acc[mi][1], a[mi], &bw[2]);
    }
}

// A fragments: m16k16 x2 (warp rows 32), row-major, SW128-swizzled smem
__device__ __forceinline__ void load_a(uint32_t (&a)[2][4], uint32_t abase,
                                       int warp_m, int kk, int lane) {
#pragma unroll
    for (int mi = 0; mi < 2; mi++) {
        uint32_t row = (uint32_t)(warp_m * 32 + mi * 16 + (lane & 15));
        uint32_t byte = row * 128u + (uint32_t)kk * 32u + ((uint32_t)(lane >> 4) << 4);
        LDSM4(a[mi], abase + swz(byte));
    }
}

// B fragments: n16 x k16 from W tile ((n,k) row-major); one ldmatrix.x4
__device__ __forceinline__ void load_b(uint32_t (&bw)[4], uint32_t wbase,
                                       int warp_n, int kk, int lane) {
    int g = lane >> 3;
    uint32_t row = (uint32_t)(warp_n * 16 + ((g >> 1) << 3) + (lane & 7));
    uint32_t byte = row * 128u + (uint32_t)kk * 32u + ((uint32_t)(g & 1) << 4);
    LDSM4(bw, wbase + swz(byte));
}

// ---------------- fp32 -> fp16 conversion ----------------
// activations: blockIdx.y = 0 -> input, 1 -> hidden
__global__ void cvt2_kernel(const float4* __restrict__ s0,
                            const float4* __restrict__ s1,
                            uint2* __restrict__ d0, uint2* __restrict__ d1,
                            int n4) {
    int i = blockIdx.x * blockDim.x + threadIdx.x;
    if (i < n4) {
        const float4* s = blockIdx.y ? s1 : s0;
        uint2* d = blockIdx.y ? d1 : d0;
        float4 v = s[i];
        __half2 a = __floats2half2_rn(v.x, v.y);
        __half2 b = __floats2half2_rn(v.z, v.w);
        uint2 u;
        u.x = *reinterpret_cast<uint32_t*>(&a);
        u.y = *reinterpret_cast<uint32_t*>(&b);
        d[i] = u;
    }
}

// all 5 weights in one launch: blockIdx.y selects the weight
__global__ void cvt5_kernel(const float4* __restrict__ s0,
                            const float4* __restrict__ s1,
                            const float4* __restrict__ s2,
                            const float4* __restrict__ s3,
                            const float4* __restrict__ s4,
                            uint2* __restrict__ dst, int n4) {
    const float4* srcs[5] = {s0, s1, s2, s3, s4};
    int i = blockIdx.x * blockDim.x + threadIdx.x;
    if (i < n4) {
        float4 v = srcs[blockIdx.y][i];
        __half2 a = __floats2half2_rn(v.x, v.y);
        __half2 b = __floats2half2_rn(v.z, v.w);
        uint2 u;
        u.x = *reinterpret_cast<uint32_t*>(&a);
        u.y = *reinterpret_cast<uint32_t*>(&b);
        dst[(size_t)blockIdx.y * n4 + i] = u;
    }
}

// ---------------- stage loader (512 threads): 9 cp.async per thread --------
__device__ __forceinline__ void load_stage(uint32_t sbase, int m_base,
                                           int n_base, int k0, int tid) {
    const int seg = tid & 7;      // 16B segment within a 128B row
    const int r0 = tid >> 3;      // 0..63
    const __half* gi = g_in + (size_t)m_base * 1024 + k0 + seg * 8;
    const __half* gh = g_h  + (size_t)m_base * 1024 + k0 + seg * 8;
#pragma unroll
    for (int it = 0; it < 2; it++) {
        uint32_t row = (uint32_t)(r0 + it * 64);
        uint32_t sw = swz(row * 128u + (uint32_t)seg * 16u);
        cp16(sbase + OFF_AIN + sw, gi + (size_t)row * 1024);
        cp16(sbase + OFF_AH  + sw, gh + (size_t)row * 1024);
    }
    const uint32_t sww = swz((uint32_t)r0 * 128u + (uint32_t)seg * 16u);
#pragma unroll
    for (int w = 0; w < 5; w++) {
        const __half* gw = g_w[w] + (size_t)(n_base + r0) * 1024 + k0 + seg * 8;
        cp16(sbase + OFF_W + w * 8192 + sww, gw);
    }
}

// ---------------- fused GRU kernel (persistent CTAs) ----------------
// grid: one CTA per SM; tiles t = blockIdx.x + gridDim.x * i, t < NTILES.
// tile t: m_base = (t >> 4) * 128, n_base = (t & 15) * 64.
// block: 512 threads; warp grid 4(m) x 4(n), warp tile 32x16.
__global__ void __launch_bounds__(512, 1)
gru_kernel(const float* __restrict__ hidden_f32,
           const float* __restrict__ b_r_i, const float* __restrict__ b_r_h,
           const float* __restrict__ b_z_i, const float* __restrict__ b_n_i,
           const float* __restrict__ b_n_h,
           float* __restrict__ out, int write2) {
    extern __shared__ __align__(1024) char smem[];
    const int tid = threadIdx.x;
    const int wid = tid >> 5;
    const int lane = tid & 31;
    const int warp_m = wid >> 2;   // 0..3
    const int warp_n = wid & 3;    // 0..3
    const uint32_t sb = smem_u32(smem);
    const uint32_t mb_full  = sb + MBAR_OFF;        // full[b]  = mb_full + 8b
    const uint32_t mb_empty = sb + MBAR_OFF + 24;   // empty[b] = mb_empty + 8b

    const int cta = blockIdx.x;
    const int g = gridDim.x;
    if (cta >= NTILES) return;
    const int ntiles_cta = (NTILES - 1 - cta) / g + 1;
    const int total_stages = ntiles_cta * 16;

    if (tid == 0) {
#pragma unroll
        for (int b = 0; b < NSTAGE; b++) {
            mbar_init(mb_full + 8 * b, NTHREADS);   // 1 cp-arrive per thread
            mbar_init(mb_empty + 8 * b, NTHREADS);  // 1 arrive per thread
        }
    }
    __syncthreads();   // mbarriers visible before any arrive

    // 5 accumulator streams (h@W_rh computed once, shared by r and z)
    float accR[2][2][4], accZ[2][2][4], accN[2][2][4], accH[2][2][4],
          accRH[2][2][4];
#pragma unroll
    for (int mi = 0; mi < 2; mi++)
#pragma unroll
        for (int ni = 0; ni < 2; ni++)
#pragma unroll
            for (int j = 0; j < 4; j++) {
                accR[mi][ni][j] = 0.f;  accZ[mi][ni][j] = 0.f;
                accN[mi][ni][j] = 0.f;  accH[mi][ni][j] = 0.f;
                accRH[mi][ni][j] = 0.f;
            }

    const int r_lane = lane >> 2;          // 0..7
    const int c_lane = (lane & 3) * 2;     // 0,2,4,6
    const size_t out2 = (size_t)B_DIM * H_DIM;

    // prologue: fill stages 0 and 1 (both in first tile; no empty wait)
    {
        const int t0 = cta;
        const int mb0 = (t0 >> 4) * 128, nb0 = (t0 & 15) * 64;
        load_stage(sb + 0 * STAGE_BYTES, mb0, nb0, 0, tid);
        cp_mbar_arrive(mb_full + 0);
        load_stage(sb + 1 * STAGE_BYTES, mb0, nb0, 64, tid);
        cp_mbar_arrive(mb_full + 8);
    }

#pragma unroll 1
    for (int s = 0; s < total_stages; s++) {
        const int b = s % NSTAGE;
        const uint32_t pf = (uint32_t)((s / NSTAGE) & 1);  // full parity
        mbar_wait(mb_full + 8 * b, pf);

        const uint32_t st = sb + b * STAGE_BYTES;
        const uint32_t wt = st + OFF_W;
#pragma unroll
        for (int kk = 0; kk < 4; kk++) {
            uint32_t ain[2][4], ah[2][4], bw[4];
            load_a(ain, st + OFF_AIN, warp_m, kk, lane);
            load_a(ah,  st + OFF_AH,  warp_m, kk, lane);

            load_b(bw, wt + 0 * 8192, warp_n, kk, lane);  // W_ri
            mma_block(accR, ain, bw);
            load_b(bw, wt + 2 * 8192, warp_n, kk, lane);  // W_zi
            mma_block(accZ, ain, bw);
            load_b(bw, wt + 3 * 8192, warp_n, kk, lane);  // W_ni
            mma_block(accN, ain, bw);
            load_b(bw, wt + 1 * 8192, warp_n, kk, lane);  // W_rh
            mma_block(accRH, ah, bw);                     // shared r/z
            load_b(bw, wt + 4 * 8192, warp_n, kk, lane);  // W_nh
            mma_block(accH, ah, bw);
        }
        mbar_arrive(mb_empty + 8 * b);   // release: LDSMs of buf b done

        // issue load for stage s+2 (may belong to the NEXT tile)
        const int ls = s + 2;
        if (ls < total_stages) {
            const int bt = ls % NSTAGE;
            // wait for (load#-1)-th consume; passes immediately for load#0
            const uint32_t pe = (uint32_t)(((ls / NSTAGE) + 1) & 1);
            mbar_wait(mb_empty + 8 * bt, pe);
            const int tl = cta + g * (ls >> 4);
            load_stage(sb + bt * STAGE_BYTES, (tl >> 4) * 128,
                       (tl & 15) * 64, (ls & 15) * 64, tid);
            cp_mbar_arrive(mb_full + 8 * bt);
        }

        // -------- tile finished: fused epilogue (loads for next tile are
        // already in flight; accs are per-thread, no CTA sync needed) ------
        if ((s & 15) == 15) {
            const int tc = cta + g * (s >> 4);
            const int m_base = (tc >> 4) * 128;
            const int n_base = (tc & 15) * 64;
#pragma unroll
            for (int ni = 0; ni < 2; ni++) {
                const int gcol = n_base + warp_n * 16 + ni * 8 + c_lane;
                float bri0 = __ldg(&b_r_i[gcol]), bri1 = __ldg(&b_r_i[gcol + 1]);
                float brh0 = __ldg(&b_r_h[gcol]), brh1 = __ldg(&b_r_h[gcol + 1]);
                float bzi0 = __ldg(&b_z_i[gcol]), bzi1 = __ldg(&b_z_i[gcol + 1]);
                float bni0 = __ldg(&b_n_i[gcol]), bni1 = __ldg(&b_n_i[gcol + 1]);
                float bnh0 = __ldg(&b_n_h[gcol]), bnh1 = __ldg(&b_n_h[gcol + 1]);
                const float br[2] = {bri0 + brh0, bri1 + brh1};
                const float bz[2] = {bzi0 + brh0, bzi1 + brh1};
                const float bn[2] = {bni0, bni1};
                const float bh[2] = {bnh0, bnh1};
#pragma unroll
                for (int mi = 0; mi < 2; mi++) {
#pragma unroll
                    for (int half = 0; half < 2; half++) {
                        const int grow = m_base + warp_m * 32 + mi * 16
                                         + half * 8 + r_lane;
                        const size_t rowoff = (size_t)grow * 1024 + gcol;
                        const float2 h2 = *(const float2*)(hidden_f32 + rowoff);
                        float o[2];
#pragma unroll
                        for (int j = 0; j < 2; j++) {
                            const int c = half * 2 + j;
                            float rh = accRH[mi][ni][c];
                            float vr = accR[mi][ni][c] + rh + br[j];
                            float vz = accZ[mi][ni][c] + rh + bz[j];
                            float vn = accN[mi][ni][c] + bn[j];
                            float vh = accH[mi][ni][c] + bh[j];
                            float rg = 1.f / (1.f + __expf(-vr));
                            float zg = 1.f / (1.f + __expf(-vz));
                            float pre = vn + rg * vh;
                            float ng = 2.f / (1.f + __expf(-2.f * pre)) - 1.f;
                            float hv = j ? h2.y : h2.x;
                            o[j] = (1.f - zg) * ng + zg * hv;
                        }
                        float2 o2; o2.x = o[0]; o2.y = o[1];
                        *(float2*)(out + rowoff) = o2;
                        if (write2) *(float2*)(out + out2 + rowoff) = o2;
                    }
                }
            }
            // reset accumulators for the next tile
#pragma unroll
            for (int mi = 0; mi < 2; mi++)
#pragma unroll
                for (int ni = 0; ni < 2; ni++)
#pragma unroll
                    for (int j = 0; j < 4; j++) {
                        accR[mi][ni][j] = 0.f;  accZ[mi][ni][j] = 0.f;
                        accN[mi][ni][j] = 0.f;  accH[mi][ni][j] = 0.f;
                        accRH[mi][ni][j] = 0.f;
                    }
        }
    }
}

// ---------------- host launch ----------------
extern "C" void kernel_launch(void* const* d_in, const int* in_sizes, int n_in,
                              void* d_out, int out_size) {
    const float* input  = (const float*)d_in[0];
    const float* hidden = (const float*)d_in[1];
    const float* W_r_i  = (const float*)d_in[2];
    const float* b_r_i  = (const float*)d_in[3];
    const float* W_r_h  = (const float*)d_in[4];
    const float* b_r_h  = (const float*)d_in[5];
    const float* W_z_i  = (const float*)d_in[6];
    const float* b_z_i  = (const float*)d_in[7];
    // d_in[8], d_in[9]: W_z_h / b_z_h — dead per reference bug
    const float* W_n_i  = (const float*)d_in[10];
    const float* b_n_i  = (const float*)d_in[11];
    const float* W_n_h  = (const float*)d_in[12];
    const float* b_n_h  = (const float*)d_in[13];
    float* out = (float*)d_out;

    void *pin, *ph, *pw;
    cudaGetSymbolAddress(&pin, g_in);
    cudaGetSymbolAddress(&ph, g_h);
    cudaGetSymbolAddress(&pw, g_w);

    const int act4 = (B_DIM * K_DIM) / 4;
    const int wt4  = (H_DIM * K_DIM) / 4;
    dim3 agrid(act4 / 256, 2);
    cvt2_kernel<<<agrid, 256>>>((const float4*)input, (const float4*)hidden,
                                (uint2*)pin, (uint2*)ph, act4);
    // weight order in g_w: ri, rh, zi, ni, nh
    dim3 wgrid(wt4 / 256, 5);
    cvt5_kernel<<<wgrid, 256>>>((const float4*)W_r_i, (const float4*)W_r_h,
                                (const float4*)W_z_i, (const float4*)W_n_i,
                                (const float4*)W_n_h, (uint2*)pw, wt4);

    static int nsm = 0;
    if (nsm == 0) {
        int dev = 0;
        cudaGetDevice(&dev);
        if (cudaDeviceGetAttribute(&nsm, cudaDevAttrMultiProcessorCount, dev)
                != cudaSuccess || nsm <= 0)
            nsm = 148;
    }
    int grid = nsm < NTILES ? nsm : NTILES;

    cudaFuncSetAttribute(gru_kernel, cudaFuncAttributeMaxDynamicSharedMemorySize,
                         SMEM_BYTES);
    int write2 = (out_size >= 2 * B_DIM * H_DIM) ? 1 : 0;
    gru_kernel<<<grid, NTHREADS, SMEM_BYTES>>>(hidden, b_r_i, b_r_h, b_z_i,
                                               b_n_i, b_n_h, out, write2);
}

// round 14
// speedup vs baseline: 1.2324x; 1.0813x over previous
#include <cuda_runtime.h>
#include <cuda_fp16.h>
#include <cstdint>

// ---------------------------------------------------------------------------
// myGRUCell fused kernel for GB300 (sm_103a harness, base sm_103 PTX target).
// tcgen05 unavailable at this PTX target; tensor work via mma.sync.m16n8k16
// (HMMA) + ldmatrix + cp.async.
//
// 5-stream formulation (h@W_rh computed ONCE, shared by r and z):
//   accR  = in@Wri^T      accRH = h@Wrh^T
//   accZ  = in@Wzi^T      accN  = in@Wni^T      accH = h@Wnh^T
//   r  = sigmoid(accR + accRH + b_ri + b_rh)
//   z  = sigmoid(accZ + accRH + b_zi + b_rh)    (reference bug: reuses r_h)
//   n  = tanh   (accN + b_ni + r*(accH + b_nh))
//   out = (1-z)*n + z*h    (written twice: tuple output)
//
// R14 (on top of R13 persistent CTAs + barrier-free mbarrier pipeline):
//  - stage-load burst split into A-half / W-half interleaved with kk compute
//  - empty-barrier arrives reduced to per-warp (lane 0, count 16)
//  - __fdividef in the epilogue activations
// ---------------------------------------------------------------------------

#define B_DIM 16384
#define K_DIM 1024
#define H_DIM 1024
#define NTILES 2048            // (B/128) * (H/64) = 128 * 16

// fp16 scratch (device globals: allocation-free per harness rules)
__device__ __half g_in[(size_t)B_DIM * K_DIM];
__device__ __half g_h [(size_t)B_DIM * K_DIM];
__device__ __half g_w [5][(size_t)H_DIM * K_DIM];   // ri, rh, zi, ni, nh

// ---- smem stage layout (BK = 64 halves = 128 bytes/row) ----
#define OFF_AIN 0            // A_in: 128 rows x 128B = 16KB
#define OFF_AH  16384        // A_h : 16KB
#define OFF_W   32768        // 5 weights x (64 rows x 128B = 8KB) = 40KB
#define STAGE_BYTES 73728    // 72KB
#define NSTAGE 3
#define MBAR_OFF (NSTAGE * STAGE_BYTES)     // 6 mbarriers: full[3], empty[3]
#define SMEM_BYTES (MBAR_OFF + 64)

#define NTHREADS 512
#define NWARPS   16

// ---------------- PTX helpers (base sm_103 instruction set only) ------------
__device__ __forceinline__ uint32_t smem_u32(const void* p) {
    uint32_t a;
    asm("{ .reg .u64 t; cvta.to.shared.u64 t, %1; cvt.u32.u64 %0, t; }"
        : "=r"(a) : "l"(p));
    return a;
}
__device__ __forceinline__ void cp16(uint32_t saddr, const void* g) {
    asm volatile("cp.async.cg.shared.global [%0], [%1], 16;\n"
                 :: "r"(saddr), "l"(g));
}
__device__ __forceinline__ void mbar_init(uint32_t a, uint32_t cnt) {
    asm volatile("mbarrier.init.shared.b64 [%0], %1;" :: "r"(a), "r"(cnt) : "memory");
}
// deferred arrive once all of this thread's prior cp.async have completed.
// .noinc: counts toward the init() expected arrivals.
__device__ __forceinline__ void cp_mbar_arrive(uint32_t a) {
    asm volatile("cp.async.mbarrier.arrive.noinc.shared.b64 [%0];" :: "r"(a) : "memory");
}
__device__ __forceinline__ void mbar_arrive(uint32_t a) {
    asm volatile("mbarrier.arrive.shared.b64 _, [%0];" :: "r"(a) : "memory");
}
// completes when the phase with the given parity completes (acquire)
__device__ __forceinline__ void mbar_wait(uint32_t a, uint32_t parity) {
    uint32_t done;
    asm volatile("{\n\t.reg .pred p;\n\t"
                 "mbarrier.try_wait.parity.acquire.cta.shared::cta.b64 p, [%1], %2;\n\t"
                 "selp.b32 %0, 1, 0, p;\n\t}"
                 : "=r"(done) : "r"(a), "r"(parity) : "memory");
    if (!done) {
        asm volatile("{\n\t.reg .pred P1;\n\t"
                     "W_%=:\n\t"
                     "mbarrier.try_wait.parity.acquire.cta.shared::cta.b64 P1, [%0], %1, 0x989680;\n\t"
                     "@P1 bra.uni D_%=;\n\t"
                     "bra.uni W_%=;\n\t"
                     "D_%=:\n\t}" :: "r"(a), "r"(parity) : "memory");
    }
}
__device__ __forceinline__ uint32_t swz(uint32_t byte) {
    return byte ^ ((byte >> 3) & 0x70u);
}
#define LDSM4(R, addr)                                                         \
    asm volatile("ldmatrix.sync.aligned.m8n8.x4.shared.b16 {%0,%1,%2,%3}, [%4];" \
        : "=r"((R)[0]), "=r"((R)[1]), "=r"((R)[2]), "=r"((R)[3]) : "r"(addr))

__device__ __forceinline__ void mma16816(float* c, const uint32_t* a,
                                         const uint32_t* b) {
    asm volatile(
        "mma.sync.aligned.m16n8k16.row.col.f32.f16.f16.f32 "
        "{%0,%1,%2,%3}, {%4,%5,%6,%7}, {%8,%9}, {%0,%1,%2,%3};"
        : "+f"(c[0]), "+f"(c[1]), "+f"(c[2]), "+f"(c[3])
        : "r"(a[0]), "r"(a[1]), "r"(a[2]), "r"(a[3]), "r"(b[0]), "r"(b[1]));
}

// one MMA stream step: warp tile 32x16, A frags a[2][4], B frag bw[4]
__device__ __forceinline__ void mma_block(float (&acc)[2][2][4],
                                          const uint32_t (&a)[2][4],
                                          const uint32_t (&bw)[4]) {
#pragma unroll
    for (int mi = 0; mi < 2; mi++) {
        mma16816(acc[mi][0], a[mi], &bw[0]);
        mma16816(acc[mi][1], a[mi], &bw[2]);
    }
}

// A fragments: m16k16 x2 (warp rows 32), row-major, SW128-swizzled smem
__device__ __forceinline__ void load_a(uint32_t (&a)[2][4], uint32_t abase,
                                       int warp_m, int kk, int lane) {
#pragma unroll
    for (int mi = 0; mi < 2; mi++) {
        uint32_t row = (uint32_t)(warp_m * 32 + mi * 16 + (lane & 15));
        uint32_t byte = row * 128u + (uint32_t)kk * 32u + ((uint32_t)(lane >> 4) << 4);
        LDSM4(a[mi], abase + swz(byte));
    }
}

// B fragments: n16 x k16 from W tile ((n,k) row-major); one ldmatrix.x4
__device__ __forceinline__ void load_b(uint32_t (&bw)[4], uint32_t wbase,
                                       int warp_n, int kk, int lane) {
    int g = lane >> 3;
    uint32_t row = (uint32_t)(warp_n * 16 + ((g >> 1) << 3) + (lane & 7));
    uint32_t byte = row * 128u + (uint32_t)kk * 32u + ((uint32_t)(g & 1) << 4);
    LDSM4(bw, wbase + swz(byte));
}

// one k-chunk of all 5 streams
__device__ __forceinline__ void compute_kk(
    uint32_t st, uint32_t wt, int warp_m, int warp_n, int kk, int lane,
    float (&accR)[2][2][4], float (&accZ)[2][2][4], float (&accN)[2][2][4],
    float (&accRH)[2][2][4], float (&accH)[2][2][4]) {
    uint32_t ain[2][4], ah[2][4], bw[4];
    load_a(ain, st + OFF_AIN, warp_m, kk, lane);
    load_a(ah,  st + OFF_AH,  warp_m, kk, lane);
    load_b(bw, wt + 0 * 8192, warp_n, kk, lane);  // W_ri
    mma_block(accR, ain, bw);
    load_b(bw, wt + 2 * 8192, warp_n, kk, lane);  // W_zi
    mma_block(accZ, ain, bw);
    load_b(bw, wt + 3 * 8192, warp_n, kk, lane);  // W_ni
    mma_block(accN, ain, bw);
    load_b(bw, wt + 1 * 8192, warp_n, kk, lane);  // W_rh
    mma_block(accRH, ah, bw);                     // shared r/z
    load_b(bw, wt + 4 * 8192, warp_n, kk, lane);  // W_nh
    mma_block(accH, ah, bw);
}

// ---------------- fp32 -> fp16 conversion ----------------
__global__ void cvt2_kernel(const float4* __restrict__ s0,
                            const float4* __restrict__ s1,
                            uint2* __restrict__ d0, uint2* __restrict__ d1,
                            int n4) {
    int i = blockIdx.x * blockDim.x + threadIdx.x;
    if (i < n4) {
        const float4* s = blockIdx.y ? s1 : s0;
        uint2* d = blockIdx.y ? d1 : d0;
        float4 v = s[i];
        __half2 a = __floats2half2_rn(v.x, v.y);
        __half2 b = __floats2half2_rn(v.z, v.w);
        uint2 u;
        u.x = *reinterpret_cast<uint32_t*>(&a);
        u.y = *reinterpret_cast<uint32_t*>(&b);
        d[i] = u;
    }
}

__global__ void cvt5_kernel(const float4* __restrict__ s0,
                            const float4* __restrict__ s1,
                            const float4* __restrict__ s2,
                            const float4* __restrict__ s3,
                            const float4* __restrict__ s4,
                            uint2* __restrict__ dst, int n4) {
    const float4* srcs[5] = {s0, s1, s2, s3, s4};
    int i = blockIdx.x * blockDim.x + threadIdx.x;
    if (i < n4) {
        float4 v = srcs[blockIdx.y][i];
        __half2 a = __floats2half2_rn(v.x, v.y);
        __half2 b = __floats2half2_rn(v.z, v.w);
        uint2 u;
        u.x = *reinterpret_cast<uint32_t*>(&a);
        u.y = *reinterpret_cast<uint32_t*>(&b);
        dst[(size_t)blockIdx.y * n4 + i] = u;
    }
}

// ---------------- stage loader halves (512 threads) ------------------------
// A half: 4 cp.async per thread (A_in + A_h, 2 rows each)
__device__ __forceinline__ void load_stage_a(uint32_t sbase, int m_base,
                                             int k0, int tid) {
    const int seg = tid & 7;
    const int r0 = tid >> 3;
    const __half* gi = g_in + (size_t)m_base * 1024 + k0 + seg * 8;
    const __half* gh = g_h  + (size_t)m_base * 1024 + k0 + seg * 8;
#pragma unroll
    for (int it = 0; it < 2; it++) {
        uint32_t row = (uint32_t)(r0 + it * 64);
        uint32_t sw = swz(row * 128u + (uint32_t)seg * 16u);
        cp16(sbase + OFF_AIN + sw, gi + (size_t)row * 1024);
        cp16(sbase + OFF_AH  + sw, gh + (size_t)row * 1024);
    }
}
// W half: 5 cp.async per thread (one row of each weight tile)
__device__ __forceinline__ void load_stage_w(uint32_t sbase, int n_base,
                                             int k0, int tid) {
    const int seg = tid & 7;
    const int r0 = tid >> 3;
    const uint32_t sww = swz((uint32_t)r0 * 128u + (uint32_t)seg * 16u);
#pragma unroll
    for (int w = 0; w < 5; w++) {
        const __half* gw = g_w[w] + (size_t)(n_base + r0) * 1024 + k0 + seg * 8;
        cp16(sbase + OFF_W + w * 8192 + sww, gw);
    }
}

// ---------------- fused GRU kernel (persistent CTAs) ----------------
// grid: one CTA per SM; tiles t = blockIdx.x + gridDim.x * i, t < NTILES.
// tile t: m_base = (t >> 4) * 128, n_base = (t & 15) * 64.
// block: 512 threads; warp grid 4(m) x 4(n), warp tile 32x16.
__global__ void __launch_bounds__(512, 1)
gru_kernel(const float* __restrict__ hidden_f32,
           const float* __restrict__ b_r_i, const float* __restrict__ b_r_h,
           const float* __restrict__ b_z_i, const float* __restrict__ b_n_i,
           const float* __restrict__ b_n_h,
           float* __restrict__ out, int write2) {
    extern __shared__ __align__(1024) char smem[];
    const int tid = threadIdx.x;
    const int wid = tid >> 5;
    const int lane = tid & 31;
    const int warp_m = wid >> 2;   // 0..3
    const int warp_n = wid & 3;    // 0..3
    const uint32_t sb = smem_u32(smem);
    const uint32_t mb_full  = sb + MBAR_OFF;        // full[b]  = mb_full + 8b
    const uint32_t mb_empty = sb + MBAR_OFF + 24;   // empty[b] = mb_empty + 8b

    const int cta = blockIdx.x;
    const int g = gridDim.x;
    if (cta >= NTILES) return;
    const int ntiles_cta = (NTILES - 1 - cta) / g + 1;
    const int total_stages = ntiles_cta * 16;

    if (tid == 0) {
#pragma unroll
        for (int b = 0; b < NSTAGE; b++) {
            mbar_init(mb_full + 8 * b, NTHREADS);   // 1 cp-arrive per thread
            mbar_init(mb_empty + 8 * b, NWARPS);    // 1 arrive per warp (lane 0)
        }
    }
    __syncthreads();   // mbarriers visible before any arrive

    // 5 accumulator streams
    float accR[2][2][4], accZ[2][2][4], accN[2][2][4], accH[2][2][4],
          accRH[2][2][4];
#pragma unroll
    for (int mi = 0; mi < 2; mi++)
#pragma unroll
        for (int ni = 0; ni < 2; ni++)
#pragma unroll
            for (int j = 0; j < 4; j++) {
                accR[mi][ni][j] = 0.f;  accZ[mi][ni][j] = 0.f;
                accN[mi][ni][j] = 0.f;  accH[mi][ni][j] = 0.f;
                accRH[mi][ni][j] = 0.f;
            }

    const int r_lane = lane >> 2;          // 0..7
    const int c_lane = (lane & 3) * 2;     // 0,2,4,6
    const size_t out2 = (size_t)B_DIM * H_DIM;

    // prologue: fill stages 0 and 1 (both in first tile; no empty wait)
    {
        const int t0 = cta;
        const int mb0 = (t0 >> 4) * 128, nb0 = (t0 & 15) * 64;
        load_stage_a(sb + 0 * STAGE_BYTES, mb0, 0, tid);
        load_stage_w(sb + 0 * STAGE_BYTES, nb0, 0, tid);
        cp_mbar_arrive(mb_full + 0);
        load_stage_a(sb + 1 * STAGE_BYTES, mb0, 64, tid);
        load_stage_w(sb + 1 * STAGE_BYTES, nb0, 64, tid);
        cp_mbar_arrive(mb_full + 8);
    }

#pragma unroll 1
    for (int s = 0; s < total_stages; s++) {
        const int b = s % NSTAGE;
        const uint32_t pf = (uint32_t)((s / NSTAGE) & 1);  // full parity
        mbar_wait(mb_full + 8 * b, pf);

        const uint32_t st = sb + b * STAGE_BYTES;
        const uint32_t wt = st + OFF_W;

        compute_kk(st, wt, warp_m, warp_n, 0, lane, accR, accZ, accN, accRH, accH);
        compute_kk(st, wt, warp_m, warp_n, 1, lane, accR, accZ, accN, accRH, accH);

        // prepare load for stage s+2 (may belong to the NEXT tile)
        const int ls = s + 2;
        const bool dl = (ls < total_stages);
        int bt = 0, lm = 0, ln = 0, lk = 0;
        if (dl) {
            bt = ls % NSTAGE;
            // wait for (load#-1)-th consume; passes immediately for load#0
            const uint32_t pe = (uint32_t)(((ls / NSTAGE) + 1) & 1);
            mbar_wait(mb_empty + 8 * bt, pe);
            const int tl = cta + g * (ls >> 4);
            lm = (tl >> 4) * 128;  ln = (tl & 15) * 64;  lk = (ls & 15) * 64;
            load_stage_a(sb + bt * STAGE_BYTES, lm, lk, tid);   // 4 cp.async
        }

        compute_kk(st, wt, warp_m, warp_n, 2, lane, accR, accZ, accN, accRH, accH);

        if (dl) load_stage_w(sb + bt * STAGE_BYTES, ln, lk, tid);  // 5 cp.async

        compute_kk(st, wt, warp_m, warp_n, 3, lane, accR, accZ, accN, accRH, accH);

        if (dl) cp_mbar_arrive(mb_full + 8 * bt);
        if (lane == 0) mbar_arrive(mb_empty + 8 * b);  // warp released buf b

        // -------- tile finished: fused epilogue --------
        if ((s & 15) == 15) {
            const int tc = cta + g * (s >> 4);
            const int m_base = (tc >> 4) * 128;
            const int n_base = (tc & 15) * 64;
#pragma unroll
            for (int ni = 0; ni < 2; ni++) {
                const int gcol = n_base + warp_n * 16 + ni * 8 + c_lane;
                float bri0 = __ldg(&b_r_i[gcol]), bri1 = __ldg(&b_r_i[gcol + 1]);
                float brh0 = __ldg(&b_r_h[gcol]), brh1 = __ldg(&b_r_h[gcol + 1]);
                float bzi0 = __ldg(&b_z_i[gcol]), bzi1 = __ldg(&b_z_i[gcol + 1]);
                float bni0 = __ldg(&b_n_i[gcol]), bni1 = __ldg(&b_n_i[gcol + 1]);
                float bnh0 = __ldg(&b_n_h[gcol]), bnh1 = __ldg(&b_n_h[gcol + 1]);
                const float br[2] = {bri0 + brh0, bri1 + brh1};
                const float bz[2] = {bzi0 + brh0, bzi1 + brh1};
                const float bn[2] = {bni0, bni1};
                const float bh[2] = {bnh0, bnh1};
#pragma unroll
                for (int mi = 0; mi < 2; mi++) {
#pragma unroll
                    for (int half = 0; half < 2; half++) {
                        const int grow = m_base + warp_m * 32 + mi * 16
                                         + half * 8 + r_lane;
                        const size_t rowoff = (size_t)grow * 1024 + gcol;
                        const float2 h2 = *(const float2*)(hidden_f32 + rowoff);
                        float o[2];
#pragma unroll
                        for (int j = 0; j < 2; j++) {
                            const int c = half * 2 + j;
                            float rh = accRH[mi][ni][c];
                            float vr = accR[mi][ni][c] + rh + br[j];
                            float vz = accZ[mi][ni][c] + rh + bz[j];
                            float vn = accN[mi][ni][c] + bn[j];
                            float vh = accH[mi][ni][c] + bh[j];
                            float rg = __fdividef(1.f, 1.f + __expf(-vr));
                            float zg = __fdividef(1.f, 1.f + __expf(-vz));
                            float pre = vn + rg * vh;
                            float ng = __fdividef(2.f, 1.f + __expf(-2.f * pre))
                                       - 1.f;
                            float hv = j ? h2.y : h2.x;
                            o[j] = (1.f - zg) * ng + zg * hv;
                        }
                        float2 o2; o2.x = o[0]; o2.y = o[1];
                        *(float2*)(out + rowoff) = o2;
                        if (write2) *(float2*)(out + out2 + rowoff) = o2;
                    }
                }
            }
            // reset accumulators for the next tile
#pragma unroll
            for (int mi = 0; mi < 2; mi++)
#pragma unroll
                for (int ni = 0; ni < 2; ni++)
#pragma unroll
                    for (int j = 0; j < 4; j++) {
                        accR[mi][ni][j] = 0.f;  accZ[mi][ni][j] = 0.f;
                        accN[mi][ni][j] = 0.f;  accH[mi][ni][j] = 0.f;
                        accRH[mi][ni][j] = 0.f;
                    }
        }
    }
}

// ---------------- host launch ----------------
extern "C" void kernel_launch(void* const* d_in, const int* in_sizes, int n_in,
                              void* d_out, int out_size) {
    const float* input  = (const float*)d_in[0];
    const float* hidden = (const float*)d_in[1];
    const float* W_r_i  = (const float*)d_in[2];
    const float* b_r_i  = (const float*)d_in[3];
    const float* W_r_h  = (const float*)d_in[4];
    const float* b_r_h  = (const float*)d_in[5];
    const float* W_z_i  = (const float*)d_in[6];
    const float* b_z_i  = (const float*)d_in[7];
    // d_in[8], d_in[9]: W_z_h / b_z_h — dead per reference bug
    const float* W_n_i  = (const float*)d_in[10];
    const float* b_n_i  = (const float*)d_in[11];
    const float* W_n_h  = (const float*)d_in[12];
    const float* b_n_h  = (const float*)d_in[13];
    float* out = (float*)d_out;

    void *pin, *ph, *pw;
    cudaGetSymbolAddress(&pin, g_in);
    cudaGetSymbolAddress(&ph, g_h);
    cudaGetSymbolAddress(&pw, g_w);

    const int act4 = (B_DIM * K_DIM) / 4;
    const int wt4  = (H_DIM * K_DIM) / 4;
    dim3 agrid(act4 / 256, 2);
    cvt2_kernel<<<agrid, 256>>>((const float4*)input, (const float4*)hidden,
                                (uint2*)pin, (uint2*)ph, act4);
    // weight order in g_w: ri, rh, zi, ni, nh
    dim3 wgrid(wt4 / 256, 5);
    cvt5_kernel<<<wgrid, 256>>>((const float4*)W_r_i, (const float4*)W_r_h,
                                (const float4*)W_z_i, (const float4*)W_n_i,
                                (const float4*)W_n_h, (uint2*)pw, wt4);

    static int nsm = 0;
    if (nsm == 0) {
        int dev = 0;
        cudaGetDevice(&dev);
        if (cudaDeviceGetAttribute(&nsm, cudaDevAttrMultiProcessorCount, dev)
                != cudaSuccess || nsm <= 0)
            nsm = 148;
    }
    int grid = nsm < NTILES ? nsm : NTILES;

    cudaFuncSetAttribute(gru_kernel, cudaFuncAttributeMaxDynamicSharedMemorySize,
                         SMEM_BYTES);
    int write2 = (out_size >= 2 * B_DIM * H_DIM) ? 1 : 0;
    gru_kernel<<<grid, NTHREADS, SMEM_BYTES>>>(hidden, b_r_i, b_r_h, b_z_i,
                                               b_n_i, b_n_h, out, write2);
}